// round 8
// baseline (speedup 1.0000x reference)
#include <cuda_runtime.h>
#include <cuda_bf16.h>
#include <cstdint>

namespace {

constexpr int SQn = 2048, SKn = 2048, Dn = 128;
constexpr float SCALE = 22.62741699796952f; // 2*sqrt(128)

constexpr int STRIDE_W = 68;             // words per padded row (128 bf16 + 16B pad)
constexpr int STRIDE_B = STRIDE_W * 4;   // 272 B
constexpr int CHUNK_ROWS = 64;
constexpr int BUF_B   = CHUNK_ROWS * STRIDE_B;  // 17408 B (one of KH,KL,VH,VL)
constexpr int STAGE_B = 4 * BUF_B;              // 69632 B per stage
constexpr int NSTAGE  = 3;
constexpr int SM_BAR  = NSTAGE * STAGE_B;       // 208896
constexpr int SMEM_TOTAL = SM_BAR + 64;         // + mbarriers
constexpr int NCHUNK = SKn / CHUNK_ROWS;        // 32

// scratch: [bh(32)][chunk(32)][buf: KH,KL,VH,VL][row(64) * 272B]
__device__ __align__(16) char g_scratch[32ull * NCHUNK * STAGE_B];

__device__ __forceinline__ uint32_t packbf(float a, float b) {
    __nv_bfloat162 t = __floats2bfloat162_rn(a, b);
    return *reinterpret_cast<uint32_t*>(&t);
}
__device__ __forceinline__ uint32_t prmt_hi(uint32_t a, uint32_t b) {
    uint32_t d; asm("prmt.b32 %0,%1,%2,0x7632;" : "=r"(d) : "r"(a), "r"(b)); return d;
}
__device__ __forceinline__ float truncbf(float x) {
    return __uint_as_float(__float_as_uint(x) & 0xFFFF0000u);
}
__device__ __forceinline__ void mma16816(float* d, const uint32_t* a, uint32_t b0, uint32_t b1) {
    asm volatile(
        "mma.sync.aligned.m16n8k16.row.col.f32.bf16.bf16.f32 "
        "{%0,%1,%2,%3}, {%4,%5,%6,%7}, {%8,%9}, {%0,%1,%2,%3};\n"
        : "+f"(d[0]), "+f"(d[1]), "+f"(d[2]), "+f"(d[3])
        : "r"(a[0]), "r"(a[1]), "r"(a[2]), "r"(a[3]), "r"(b0), "r"(b1));
}
__device__ __forceinline__ void ldsm4(uint32_t* r, uint32_t saddr) {
    asm volatile("ldmatrix.sync.aligned.m8n8.x4.shared.b16 {%0,%1,%2,%3}, [%4];\n"
                 : "=r"(r[0]), "=r"(r[1]), "=r"(r[2]), "=r"(r[3]) : "r"(saddr));
}
__device__ __forceinline__ void ldsm4t(uint32_t* r, uint32_t saddr) {
    asm volatile("ldmatrix.sync.aligned.m8n8.x4.trans.shared.b16 {%0,%1,%2,%3}, [%4];\n"
                 : "=r"(r[0]), "=r"(r[1]), "=r"(r[2]), "=r"(r[3]) : "r"(saddr));
}
__device__ __forceinline__ void cp16(uint32_t sdst, const void* gsrc) {
    asm volatile("cp.async.cg.shared.global [%0], [%1], 16;" :: "r"(sdst), "l"(gsrc) : "memory");
}
__device__ __forceinline__ void cp_mbar_arrive(uint32_t mbar) {
    asm volatile("cp.async.mbarrier.arrive.noinc.shared.b64 [%0];" :: "r"(mbar) : "memory");
}
__device__ __forceinline__ void mbar_init(uint32_t a, uint32_t n) {
    asm volatile("mbarrier.init.shared.b64 [%0], %1;" :: "r"(a), "r"(n) : "memory");
}
__device__ __forceinline__ void mbar_arrive(uint32_t a) {
    asm volatile("mbarrier.arrive.shared.b64 _, [%0];" :: "r"(a) : "memory");
}
__device__ __forceinline__ void mbar_wait(uint32_t a, uint32_t parity) {
    asm volatile("{\n\t.reg .pred P;\n\tWL_%=:\n\t"
                 "mbarrier.try_wait.parity.acquire.cta.shared::cta.b64 P, [%0], %1, 0x989680;\n\t"
                 "@P bra WD_%=;\n\tbra WL_%=;\n\tWD_%=:\n\t}"
                 :: "r"(a), "r"(parity) : "memory");
}

// ---------------- pre-pass: K,V fp32 -> hi/lo bf16 scratch ----------------
__global__ __launch_bounds__(256) void prepass(const float* __restrict__ K,
                                               const float* __restrict__ V) {
    uint32_t g = blockIdx.x * 256u + threadIdx.x;   // 0 .. 4194303
    int c4 = g & 31;                 // float4 within row
    int r  = (g >> 5) & 2047;        // key row
    int bh = (g >> 16) & 31;
    int tv = g >> 21;                // 0 = K, 1 = V
    const float* src = (tv ? V : K) + (((size_t)bh * SKn + r) * Dn + c4 * 4);
    float4 f = *reinterpret_cast<const float4*>(src);
    uint32_t bx = __float_as_uint(f.x), by = __float_as_uint(f.y);
    uint32_t bz = __float_as_uint(f.z), bw = __float_as_uint(f.w);
    uint2 hi = make_uint2(prmt_hi(bx, by), prmt_hi(bz, bw));
    uint2 lo = make_uint2(packbf(f.x - truncbf(f.x), f.y - truncbf(f.y)),
                          packbf(f.z - truncbf(f.z), f.w - truncbf(f.w)));
    char* base = g_scratch
        + (((size_t)bh * NCHUNK + (r >> 6)) * 4 + (tv ? 2 : 0)) * (size_t)BUF_B
        + (r & 63) * STRIDE_B + c4 * 8;
    *reinterpret_cast<uint2*>(base)         = hi;
    *reinterpret_cast<uint2*>(base + BUF_B) = lo;
}

// ---------------- main kernel ----------------
__global__ __launch_bounds__(256, 1) void attn_kernel(
    const float* __restrict__ Q, const int* __restrict__ M, float* __restrict__ O)
{
    extern __shared__ char smem[];
    const uint32_t sb = (uint32_t)__cvta_generic_to_shared(smem);

    // Q overlays stage 0 (dead after fragment hoist)
    uint32_t* Qh = reinterpret_cast<uint32_t*>(smem);
    uint32_t* Ql = reinterpret_cast<uint32_t*>(smem + 2 * BUF_B);
    const uint32_t sQh = sb, sQl = sb + 2 * BUF_B;

    const int tid  = threadIdx.x;
    const int warp = tid >> 5, lane = tid & 31;
    const int gid  = lane >> 2, qid = lane & 3;
    const int qr   = warp * 16;

    const int bh = blockIdx.y;
    const int qt = blockIdx.x;

    const float* Qg = Q + ((size_t)bh * SQn + (size_t)qt * 128) * Dn;
    const int*   Mg = M + ((size_t)bh * SQn + (size_t)qt * 128) * SKn;
    float*       Og = O + ((size_t)bh * SQn + (size_t)qt * 128) * Dn;
    const char*  Sg = g_scratch + (size_t)bh * NCHUNK * STAGE_B;

    // mbarriers: full[s] at SM_BAR + 8s, empty[s] at SM_BAR + 24 + 8s
    uint32_t fullB[NSTAGE], emptyB[NSTAGE];
    #pragma unroll
    for (int s = 0; s < NSTAGE; ++s) {
        fullB[s]  = sb + SM_BAR + 8 * s;
        emptyB[s] = sb + SM_BAR + 24 + 8 * s;
    }
    if (tid == 0) {
        #pragma unroll
        for (int s = 0; s < NSTAGE; ++s) { mbar_init(fullB[s], 256); mbar_init(emptyB[s], 256); }
    }

    // lane-derived ldmatrix offsets (bytes)
    const uint32_t bkOff = ((lane & 7) + ((lane >> 4) & 1) * 8) * STRIDE_B + ((lane >> 3) & 1) * 16;
    const uint32_t vOff  = ((lane & 7) + ((lane >> 3) & 1) * 8) * STRIDE_B + ((lane >> 4) & 1) * 16;
    const uint32_t qOff  = (qr + (lane & 15)) * STRIDE_B + ((lane >> 4) & 1) * 16;

    // per-thread cp.async offsets within a stage (16 x 16B)
    uint32_t cpoff[16];
    #pragma unroll
    for (int i = 0; i < 16; ++i) {
        int g = i * 256 + tid;              // 0..4095
        int buf = g >> 10, idx = g & 1023;
        int row = idx >> 4, col = idx & 15;
        cpoff[i] = buf * BUF_B + row * STRIDE_B + col * 16;
    }

    // ---- Q tile: global -> smem (hi/lo) ----
    {
        const float4* src = reinterpret_cast<const float4*>(Qg);
        #pragma unroll
        for (int it = 0; it < 16; ++it) {
            int idx = tid + it * 256;
            int row = idx >> 5, c4 = idx & 31;
            float4 v = src[idx];
            uint32_t bx = __float_as_uint(v.x), by = __float_as_uint(v.y);
            uint32_t bz = __float_as_uint(v.z), bw = __float_as_uint(v.w);
            int off = row * STRIDE_W + c4 * 2;
            *reinterpret_cast<uint2*>(Qh + off) = make_uint2(prmt_hi(bx, by), prmt_hi(bz, bw));
            *reinterpret_cast<uint2*>(Ql + off) =
                make_uint2(packbf(v.x - truncbf(v.x), v.y - truncbf(v.y)),
                           packbf(v.z - truncbf(v.z), v.w - truncbf(v.w)));
        }
    }
    __syncthreads();  // Q stored + mbarriers initialized

    // ---- hoist Q fragments (invariant across chunks) ----
    uint32_t qfh[8][4], qfl[8][4];
    #pragma unroll
    for (int ds = 0; ds < 8; ++ds) {
        ldsm4(qfh[ds], sQh + qOff + ds * 32);
        ldsm4(qfl[ds], sQl + qOff + ds * 32);
    }
    __syncthreads();  // all warps done reading Q before stage 0 is overwritten

    // ---- prologue: produce chunks 0,1 ----
    #pragma unroll
    for (int n = 0; n < 2; ++n) {
        const char* gb = Sg + (size_t)n * STAGE_B;
        const uint32_t sn = sb + n * STAGE_B;
        #pragma unroll
        for (int i = 0; i < 16; ++i) cp16(sn + cpoff[i], gb + cpoff[i]);
        cp_mbar_arrive(fullB[n]);
    }

    float o[16][4];
    #pragma unroll
    for (int i = 0; i < 16; ++i)
        #pragma unroll
        for (int j = 0; j < 4; ++j) o[i][j] = 0.f;

    #pragma unroll 1
    for (int c = 0; c < NCHUNK; ++c) {
        // ---- produce chunk c+2 ----
        const int n = c + 2;
        if (n < NCHUNK) {
            const int sn_i = n - (n / NSTAGE) * NSTAGE;   // n % 3
            if (n >= NSTAGE) mbar_wait(emptyB[sn_i], ((n - NSTAGE) / NSTAGE) & 1);
            const char* gb = Sg + (size_t)n * STAGE_B;
            const uint32_t sn = sb + sn_i * STAGE_B;
            #pragma unroll
            for (int i = 0; i < 16; ++i) cp16(sn + cpoff[i], gb + cpoff[i]);
            cp_mbar_arrive(fullB[sn_i]);
        }

        // ---- mask prefetch for the whole chunk (hide DRAM under wait/GEMM) ----
        int2 ma[2][4], mb[2][4];
        {
            const int* m0 = Mg + (size_t)(qr + gid) * SKn + c * CHUNK_ROWS + qid * 2;
            const int* m1 = m0 + 8 * (size_t)SKn;
            #pragma unroll
            for (int nc = 0; nc < 2; ++nc)
                #pragma unroll
                for (int j = 0; j < 4; ++j) {
                    ma[nc][j] = *reinterpret_cast<const int2*>(m0 + nc * 32 + j * 8);
                    mb[nc][j] = *reinterpret_cast<const int2*>(m1 + nc * 32 + j * 8);
                }
        }

        const int st_i = c - (c / NSTAGE) * NSTAGE;       // c % 3
        mbar_wait(fullB[st_i], (c / NSTAGE) & 1);

        const uint32_t st = sb + st_i * STAGE_B;
        const uint32_t sKH = st, sKL = st + BUF_B, sVH = st + 2 * BUF_B, sVL = st + 3 * BUF_B;

        #pragma unroll
        for (int nc = 0; nc < 2; ++nc) {
            const int kb = nc * 32;

            // ---- GEMM1: S[16q x 32k] = Q·K^T (bf16x3) ----
            float s[4][4];
            #pragma unroll
            for (int j = 0; j < 4; ++j) { s[j][0]=0.f; s[j][1]=0.f; s[j][2]=0.f; s[j][3]=0.f; }

            #pragma unroll
            for (int ds = 0; ds < 8; ++ds) {
                uint32_t bh0[4], bh1[4], bl0[4], bl1[4];
                const uint32_t kcol = bkOff + ds * 32;
                ldsm4(bh0, sKH + (uint32_t)(kb     ) * STRIDE_B + kcol);
                ldsm4(bh1, sKH + (uint32_t)(kb + 16) * STRIDE_B + kcol);
                ldsm4(bl0, sKL + (uint32_t)(kb     ) * STRIDE_B + kcol);
                ldsm4(bl1, sKL + (uint32_t)(kb + 16) * STRIDE_B + kcol);
                mma16816(s[0], qfh[ds], bh0[0], bh0[1]);
                mma16816(s[1], qfh[ds], bh0[2], bh0[3]);
                mma16816(s[2], qfh[ds], bh1[0], bh1[1]);
                mma16816(s[3], qfh[ds], bh1[2], bh1[3]);
                mma16816(s[0], qfl[ds], bh0[0], bh0[1]);
                mma16816(s[1], qfl[ds], bh0[2], bh0[3]);
                mma16816(s[2], qfl[ds], bh1[0], bh1[1]);
                mma16816(s[3], qfl[ds], bh1[2], bh1[3]);
                mma16816(s[0], qfh[ds], bl0[0], bl0[1]);
                mma16816(s[1], qfh[ds], bl0[2], bl0[3]);
                mma16816(s[2], qfh[ds], bl1[0], bl1[1]);
                mma16816(s[3], qfh[ds], bl1[2], bl1[3]);
            }

            // ---- mask + scale -> P ----
            float p[4][4];
            #pragma unroll
            for (int j = 0; j < 4; ++j) {
                p[j][0] = ma[nc][j].x ? s[j][0] * SCALE : 0.f;
                p[j][1] = ma[nc][j].y ? s[j][1] * SCALE : 0.f;
                p[j][2] = mb[nc][j].x ? s[j][2] * SCALE : 0.f;
                p[j][3] = mb[nc][j].y ? s[j][3] * SCALE : 0.f;
            }

            // ---- GEMM2: O += P[16x32]·V[32x128], paired tiles (accum distance 4) ----
            #pragma unroll
            for (int kk = 0; kk < 2; ++kk) {
                uint32_t ahi[4], alo[4];
                {
                    const float* p0 = p[kk*2 + 0];
                    const float* p1 = p[kk*2 + 1];
                    ahi[0] = prmt_hi(__float_as_uint(p0[0]), __float_as_uint(p0[1]));
                    ahi[1] = prmt_hi(__float_as_uint(p0[2]), __float_as_uint(p0[3]));
                    ahi[2] = prmt_hi(__float_as_uint(p1[0]), __float_as_uint(p1[1]));
                    ahi[3] = prmt_hi(__float_as_uint(p1[2]), __float_as_uint(p1[3]));
                    alo[0] = packbf(p0[0] - truncbf(p0[0]), p0[1] - truncbf(p0[1]));
                    alo[1] = packbf(p0[2] - truncbf(p0[2]), p0[3] - truncbf(p0[3]));
                    alo[2] = packbf(p1[0] - truncbf(p1[0]), p1[1] - truncbf(p1[1]));
                    alo[3] = packbf(p1[2] - truncbf(p1[2]), p1[3] - truncbf(p1[3]));
                }
                const uint32_t vbase = (uint32_t)(kb + kk * 16) * STRIDE_B + vOff;

                #pragma unroll
                for (int tp = 0; tp < 4; ++tp) {   // pairs of d-tiles
                    uint32_t vh0[4], vl0[4], vh1[4], vl1[4];
                    ldsm4t(vh0, sVH + vbase + (2*tp    ) * 32);
                    ldsm4t(vl0, sVL + vbase + (2*tp    ) * 32);
                    ldsm4t(vh1, sVH + vbase + (2*tp + 1) * 32);
                    ldsm4t(vl1, sVL + vbase + (2*tp + 1) * 32);
                    float* o0 = o[4*tp + 0];
                    float* o1 = o[4*tp + 1];
                    float* o2 = o[4*tp + 2];
                    float* o3 = o[4*tp + 3];
                    mma16816(o0, ahi, vh0[0], vh0[1]);
                    mma16816(o1, ahi, vh0[2], vh0[3]);
                    mma16816(o2, ahi, vh1[0], vh1[1]);
                    mma16816(o3, ahi, vh1[2], vh1[3]);
                    mma16816(o0, alo, vh0[0], vh0[1]);
                    mma16816(o1, alo, vh0[2], vh0[3]);
                    mma16816(o2, alo, vh1[0], vh1[1]);
                    mma16816(o3, alo, vh1[2], vh1[3]);
                    mma16816(o0, ahi, vl0[0], vl0[1]);
                    mma16816(o1, ahi, vl0[2], vl0[3]);
                    mma16816(o2, ahi, vl1[0], vl1[1]);
                    mma16816(o3, ahi, vl1[2], vl1[3]);
                }
            }
        }

        mbar_arrive(emptyB[st_i]);   // stage consumed
    }

    // ---- epilogue ----
    float* o0 = Og + (size_t)(qr + gid) * Dn + qid * 2;
    float* o1 = o0 + 8 * Dn;
    #pragma unroll
    for (int nd = 0; nd < 16; ++nd) {
        *reinterpret_cast<float2*>(o0 + nd * 8) = make_float2(o[nd][0], o[nd][1]);
        *reinterpret_cast<float2*>(o1 + nd * 8) = make_float2(o[nd][2], o[nd][3]);
    }
}

} // namespace

extern "C" void kernel_launch(void* const* d_in, const int* in_sizes, int n_in,
                              void* d_out, int out_size) {
    (void)in_sizes; (void)n_in; (void)out_size;
    const float* Q = (const float*)d_in[0];
    const float* K = (const float*)d_in[1];
    const float* V = (const float*)d_in[2];
    const int*   M = (const int*)d_in[3];
    float*       O = (float*)d_out;

    prepass<<<16384, 256>>>(K, V);

    cudaFuncSetAttribute(attn_kernel, cudaFuncAttributeMaxDynamicSharedMemorySize, SMEM_TOTAL);
    dim3 grid(SQn / 128, 32);
    attn_kernel<<<grid, 256, SMEM_TOTAL>>>(Q, M, O);
}

// round 9
// speedup vs baseline: 1.8088x; 1.8088x over previous
#include <cuda_runtime.h>
#include <cuda_bf16.h>
#include <cstdint>

namespace {

constexpr int SQn = 2048, SKn = 2048, Dn = 128;
constexpr float SCALE = 22.62741699796952f; // 2*sqrt(128)

constexpr int STRIDE_W = 68;             // words per padded row (128 bf16 + 16B pad)
constexpr int STRIDE_B = STRIDE_W * 4;   // 272 B
constexpr int CHUNK_ROWS = 64;
constexpr int BUF_B   = CHUNK_ROWS * STRIDE_B;  // 17408 B (one of KH,KL,VH,VL)
constexpr int STAGE_B = 4 * BUF_B;              // 69632 B per stage
constexpr int NSTAGE  = 3;
constexpr int SMEM_TOTAL = NSTAGE * STAGE_B;    // 208896 B
constexpr int NCHUNK = SKn / CHUNK_ROWS;        // 32

// scratch: [bh(32)][chunk(32)][buf: KH,KL,VH,VL][row(64) * 272B]
__device__ __align__(16) char g_scratch[32ull * NCHUNK * STAGE_B];

__device__ __forceinline__ uint32_t packbf(float a, float b) {
    __nv_bfloat162 t = __floats2bfloat162_rn(a, b);
    return *reinterpret_cast<uint32_t*>(&t);
}
__device__ __forceinline__ uint32_t prmt_hi(uint32_t a, uint32_t b) {
    uint32_t d; asm("prmt.b32 %0,%1,%2,0x7632;" : "=r"(d) : "r"(a), "r"(b)); return d;
}
__device__ __forceinline__ float truncbf(float x) {
    return __uint_as_float(__float_as_uint(x) & 0xFFFF0000u);
}
__device__ __forceinline__ void mma16816(float* d, const uint32_t* a, uint32_t b0, uint32_t b1) {
    asm volatile(
        "mma.sync.aligned.m16n8k16.row.col.f32.bf16.bf16.f32 "
        "{%0,%1,%2,%3}, {%4,%5,%6,%7}, {%8,%9}, {%0,%1,%2,%3};\n"
        : "+f"(d[0]), "+f"(d[1]), "+f"(d[2]), "+f"(d[3])
        : "r"(a[0]), "r"(a[1]), "r"(a[2]), "r"(a[3]), "r"(b0), "r"(b1));
}
__device__ __forceinline__ void ldsm4(uint32_t* r, uint32_t saddr) {
    asm volatile("ldmatrix.sync.aligned.m8n8.x4.shared.b16 {%0,%1,%2,%3}, [%4];\n"
                 : "=r"(r[0]), "=r"(r[1]), "=r"(r[2]), "=r"(r[3]) : "r"(saddr));
}
__device__ __forceinline__ void ldsm4t(uint32_t* r, uint32_t saddr) {
    asm volatile("ldmatrix.sync.aligned.m8n8.x4.trans.shared.b16 {%0,%1,%2,%3}, [%4];\n"
                 : "=r"(r[0]), "=r"(r[1]), "=r"(r[2]), "=r"(r[3]) : "r"(saddr));
}
__device__ __forceinline__ void cp16(uint32_t sdst, const void* gsrc) {
    asm volatile("cp.async.cg.shared.global [%0], [%1], 16;" :: "r"(sdst), "l"(gsrc) : "memory");
}
#define CP_COMMIT() asm volatile("cp.async.commit_group;" ::: "memory")
#define CP_WAIT(n)  asm volatile("cp.async.wait_group %0;" :: "n"(n) : "memory")

__device__ __forceinline__ void bar_syncg(int id) {
    asm volatile("bar.sync %0, 256;" :: "r"(id) : "memory");
}
__device__ __forceinline__ void bar_arriveg(int id) {
    asm volatile("bar.arrive %0, 256;" :: "r"(id) : "memory");
}

// ---------------- pre-pass: K,V fp32 -> hi/lo bf16 scratch ----------------
__global__ __launch_bounds__(256) void prepass(const float* __restrict__ K,
                                               const float* __restrict__ V) {
    uint32_t g = blockIdx.x * 256u + threadIdx.x;   // 0 .. 4194303
    int c4 = g & 31;                 // float4 within row
    int r  = (g >> 5) & 2047;        // key row
    int bh = (g >> 16) & 31;
    int tv = g >> 21;                // 0 = K, 1 = V
    const float* src = (tv ? V : K) + (((size_t)bh * SKn + r) * Dn + c4 * 4);
    float4 f = *reinterpret_cast<const float4*>(src);
    uint32_t bx = __float_as_uint(f.x), by = __float_as_uint(f.y);
    uint32_t bz = __float_as_uint(f.z), bw = __float_as_uint(f.w);
    uint2 hi = make_uint2(prmt_hi(bx, by), prmt_hi(bz, bw));
    uint2 lo = make_uint2(packbf(f.x - truncbf(f.x), f.y - truncbf(f.y)),
                          packbf(f.z - truncbf(f.z), f.w - truncbf(f.w)));
    char* base = g_scratch
        + (((size_t)bh * NCHUNK + (r >> 6)) * 4 + (tv ? 2 : 0)) * (size_t)BUF_B
        + (r & 63) * STRIDE_B + c4 * 8;
    *reinterpret_cast<uint2*>(base)         = hi;
    *reinterpret_cast<uint2*>(base + BUF_B) = lo;
}

// ---------------- main kernel ----------------
__global__ __launch_bounds__(256, 1) void attn_kernel(
    const float* __restrict__ Q, const int* __restrict__ M, float* __restrict__ O)
{
    extern __shared__ char smem[];
    const uint32_t sb = (uint32_t)__cvta_generic_to_shared(smem);

    // Q overlays stage 0 (dead after fragment hoist)
    uint32_t* Qh = reinterpret_cast<uint32_t*>(smem);
    uint32_t* Ql = reinterpret_cast<uint32_t*>(smem + 2 * BUF_B);
    const uint32_t sQh = sb, sQl = sb + 2 * BUF_B;

    const int tid  = threadIdx.x;
    const int warp = tid >> 5, lane = tid & 31;
    const int gid  = lane >> 2, qid = lane & 3;
    const int qr   = warp * 16;
    const int grp  = warp >> 2;   // 0: producer+lead (rows 0-63), 1: lagging (rows 64-127)

    const int bh = blockIdx.y;
    const int qt = blockIdx.x;

    const float* Qg = Q + ((size_t)bh * SQn + (size_t)qt * 128) * Dn;
    const int*   Mg = M + ((size_t)bh * SQn + (size_t)qt * 128) * SKn;
    float*       Og = O + ((size_t)bh * SQn + (size_t)qt * 128) * Dn;
    const char*  Sg = g_scratch + (size_t)bh * NCHUNK * STAGE_B;

    // lane-derived ldmatrix offsets (bytes)
    const uint32_t bkOff = ((lane & 7) + ((lane >> 4) & 1) * 8) * STRIDE_B + ((lane >> 3) & 1) * 16;
    const uint32_t vOff  = ((lane & 7) + ((lane >> 3) & 1) * 8) * STRIDE_B + ((lane >> 4) & 1) * 16;
    const uint32_t qOff  = (qr + (lane & 15)) * STRIDE_B + ((lane >> 4) & 1) * 16;

    // ---- Q tile: global -> smem (hi/lo) ----
    {
        const float4* src = reinterpret_cast<const float4*>(Qg);
        #pragma unroll
        for (int it = 0; it < 16; ++it) {
            int idx = tid + it * 256;
            int row = idx >> 5, c4 = idx & 31;
            float4 v = src[idx];
            uint32_t bx = __float_as_uint(v.x), by = __float_as_uint(v.y);
            uint32_t bz = __float_as_uint(v.z), bw = __float_as_uint(v.w);
            int off = row * STRIDE_W + c4 * 2;
            *reinterpret_cast<uint2*>(Qh + off) = make_uint2(prmt_hi(bx, by), prmt_hi(bz, bw));
            *reinterpret_cast<uint2*>(Ql + off) =
                make_uint2(packbf(v.x - truncbf(v.x), v.y - truncbf(v.y)),
                           packbf(v.z - truncbf(v.z), v.w - truncbf(v.w)));
        }
    }
    __syncthreads();

    // ---- hoist Q fragments (invariant across chunks) ----
    uint32_t qfh[8][4], qfl[8][4];
    #pragma unroll
    for (int ds = 0; ds < 8; ++ds) {
        ldsm4(qfh[ds], sQh + qOff + ds * 32);
        ldsm4(qfl[ds], sQl + qOff + ds * 32);
    }
    __syncthreads();   // Q reads done before stage 0 is overwritten

    // ---- g0 prologue: issue chunks 0,1 into stages 0,1 ----
    if (grp == 0) {
        #pragma unroll
        for (int n = 0; n < 2; ++n) {
            const char* gb = Sg + (size_t)n * STAGE_B;
            const uint32_t sn = sb + n * STAGE_B;
            #pragma unroll 4
            for (int i = 0; i < 32; ++i) {
                int idx = i * 128 + tid;              // tid < 128 for grp 0
                int buf = idx >> 10, w = idx & 1023;
                uint32_t off = buf * BUF_B + (w >> 4) * STRIDE_B + (w & 15) * 16;
                cp16(sn + off, gb + off);
            }
            CP_COMMIT();
        }
    }

    float o[16][4];
    #pragma unroll
    for (int i = 0; i < 16; ++i)
        #pragma unroll
        for (int j = 0; j < 4; ++j) o[i][j] = 0.f;

    #pragma unroll 1
    for (int c = 0; c < NCHUNK; ++c) {
        const int st_i = c - (c / NSTAGE) * NSTAGE;     // c % 3

        // ---- acquire chunk c ----
        if (grp == 0) {
            CP_WAIT(1);          // pending <= {c+1}; chunk c complete
        } else {
            bar_syncg(1 + st_i); // g0 finished computing c
        }

        const uint32_t st = sb + st_i * STAGE_B;
        const uint32_t sKH = st, sKL = st + BUF_B, sVH = st + 2 * BUF_B, sVL = st + 3 * BUF_B;
        const int koff = c * CHUNK_ROWS;

        #pragma unroll
        for (int nc = 0; nc < 2; ++nc) {
            const int kb = nc * 32;

            // mask prefetch
            const int* m0 = Mg + (size_t)(qr + gid) * SKn + koff + kb + qid * 2;
            const int* m1 = m0 + 8 * (size_t)SKn;
            int2 ma[4], mb[4];
            #pragma unroll
            for (int j = 0; j < 4; ++j) {
                ma[j] = *reinterpret_cast<const int2*>(m0 + j * 8);
                mb[j] = *reinterpret_cast<const int2*>(m1 + j * 8);
            }

            // ---- GEMM1: S[16q x 32k] = Q·K^T (bf16x3) ----
            float s[4][4];
            #pragma unroll
            for (int j = 0; j < 4; ++j) { s[j][0]=0.f; s[j][1]=0.f; s[j][2]=0.f; s[j][3]=0.f; }

            #pragma unroll
            for (int ds = 0; ds < 8; ++ds) {
                uint32_t bh0[4], bh1[4], bl0[4], bl1[4];
                const uint32_t kcol = bkOff + ds * 32;
                ldsm4(bh0, sKH + (uint32_t)(kb     ) * STRIDE_B + kcol);
                ldsm4(bh1, sKH + (uint32_t)(kb + 16) * STRIDE_B + kcol);
                ldsm4(bl0, sKL + (uint32_t)(kb     ) * STRIDE_B + kcol);
                ldsm4(bl1, sKL + (uint32_t)(kb + 16) * STRIDE_B + kcol);
                mma16816(s[0], qfh[ds], bh0[0], bh0[1]);
                mma16816(s[1], qfh[ds], bh0[2], bh0[3]);
                mma16816(s[2], qfh[ds], bh1[0], bh1[1]);
                mma16816(s[3], qfh[ds], bh1[2], bh1[3]);
                mma16816(s[0], qfl[ds], bh0[0], bh0[1]);
                mma16816(s[1], qfl[ds], bh0[2], bh0[3]);
                mma16816(s[2], qfl[ds], bh1[0], bh1[1]);
                mma16816(s[3], qfl[ds], bh1[2], bh1[3]);
                mma16816(s[0], qfh[ds], bl0[0], bl0[1]);
                mma16816(s[1], qfh[ds], bl0[2], bl0[3]);
                mma16816(s[2], qfh[ds], bl1[0], bl1[1]);
                mma16816(s[3], qfh[ds], bl1[2], bl1[3]);
            }

            // ---- mask + scale -> P ----
            float p[4][4];
            #pragma unroll
            for (int j = 0; j < 4; ++j) {
                p[j][0] = ma[j].x ? s[j][0] * SCALE : 0.f;
                p[j][1] = ma[j].y ? s[j][1] * SCALE : 0.f;
                p[j][2] = mb[j].x ? s[j][2] * SCALE : 0.f;
                p[j][3] = mb[j].y ? s[j][3] * SCALE : 0.f;
            }

            // ---- GEMM2: O += P[16x32]·V[32x128], paired d-tiles ----
            #pragma unroll
            for (int kk = 0; kk < 2; ++kk) {
                uint32_t ahi[4], alo[4];
                {
                    const float* p0 = p[kk*2 + 0];
                    const float* p1 = p[kk*2 + 1];
                    ahi[0] = prmt_hi(__float_as_uint(p0[0]), __float_as_uint(p0[1]));
                    ahi[1] = prmt_hi(__float_as_uint(p0[2]), __float_as_uint(p0[3]));
                    ahi[2] = prmt_hi(__float_as_uint(p1[0]), __float_as_uint(p1[1]));
                    ahi[3] = prmt_hi(__float_as_uint(p1[2]), __float_as_uint(p1[3]));
                    alo[0] = packbf(p0[0] - truncbf(p0[0]), p0[1] - truncbf(p0[1]));
                    alo[1] = packbf(p0[2] - truncbf(p0[2]), p0[3] - truncbf(p0[3]));
                    alo[2] = packbf(p1[0] - truncbf(p1[0]), p1[1] - truncbf(p1[1]));
                    alo[3] = packbf(p1[2] - truncbf(p1[2]), p1[3] - truncbf(p1[3]));
                }
                const uint32_t vbase = (uint32_t)(kb + kk * 16) * STRIDE_B + vOff;

                #pragma unroll
                for (int tp = 0; tp < 4; ++tp) {
                    uint32_t vh0[4], vl0[4], vh1[4], vl1[4];
                    ldsm4t(vh0, sVH + vbase + (2*tp    ) * 32);
                    ldsm4t(vl0, sVL + vbase + (2*tp    ) * 32);
                    ldsm4t(vh1, sVH + vbase + (2*tp + 1) * 32);
                    ldsm4t(vl1, sVL + vbase + (2*tp + 1) * 32);
                    float* o0 = o[4*tp + 0];
                    float* o1 = o[4*tp + 1];
                    float* o2 = o[4*tp + 2];
                    float* o3 = o[4*tp + 3];
                    mma16816(o0, ahi, vh0[0], vh0[1]);
                    mma16816(o1, ahi, vh0[2], vh0[3]);
                    mma16816(o2, ahi, vh1[0], vh1[1]);
                    mma16816(o3, ahi, vh1[2], vh1[3]);
                    mma16816(o0, alo, vh0[0], vh0[1]);
                    mma16816(o1, alo, vh0[2], vh0[3]);
                    mma16816(o2, alo, vh1[0], vh1[1]);
                    mma16816(o3, alo, vh1[2], vh1[3]);
                    mma16816(o0, ahi, vl0[0], vl0[1]);
                    mma16816(o1, ahi, vl0[2], vl0[3]);
                    mma16816(o2, ahi, vl1[0], vl1[1]);
                    mma16816(o3, ahi, vl1[2], vl1[3]);
                }
            }
        }

        // ---- release / refill ----
        if (grp == 0) {
            bar_arriveg(1 + st_i);                     // full: g1 may start chunk c
            const int n = c + 2;
            if (n < NCHUNK) {
                const int sn_i = n - (n / NSTAGE) * NSTAGE;
                if (c >= 1) bar_syncg(4 + sn_i);       // empty: g1 finished chunk c-1
                const char* gb = Sg + (size_t)n * STAGE_B;
                const uint32_t sn = sb + sn_i * STAGE_B;
                #pragma unroll 4
                for (int i = 0; i < 32; ++i) {
                    int idx = i * 128 + tid;
                    int buf = idx >> 10, w = idx & 1023;
                    uint32_t off = buf * BUF_B + (w >> 4) * STRIDE_B + (w & 15) * 16;
                    cp16(sn + off, gb + off);
                }
            }
            CP_COMMIT();   // always commit (possibly empty group) to keep counts uniform
        } else {
            bar_arriveg(4 + st_i);                     // empty: g1 done with chunk c
        }
    }

    // ---- epilogue ----
    float* o0 = Og + (size_t)(qr + gid) * Dn + qid * 2;
    float* o1 = o0 + 8 * Dn;
    #pragma unroll
    for (int nd = 0; nd < 16; ++nd) {
        *reinterpret_cast<float2*>(o0 + nd * 8) = make_float2(o[nd][0], o[nd][1]);
        *reinterpret_cast<float2*>(o1 + nd * 8) = make_float2(o[nd][2], o[nd][3]);
    }
}

} // namespace

extern "C" void kernel_launch(void* const* d_in, const int* in_sizes, int n_in,
                              void* d_out, int out_size) {
    (void)in_sizes; (void)n_in; (void)out_size;
    const float* Q = (const float*)d_in[0];
    const float* K = (const float*)d_in[1];
    const float* V = (const float*)d_in[2];
    const int*   M = (const int*)d_in[3];
    float*       O = (float*)d_out;

    prepass<<<16384, 256>>>(K, V);

    cudaFuncSetAttribute(attn_kernel, cudaFuncAttributeMaxDynamicSharedMemorySize, SMEM_TOTAL);
    dim3 grid(SQn / 128, 32);
    attn_kernel<<<grid, 256, SMEM_TOTAL>>>(Q, M, O);
}

// round 10
// speedup vs baseline: 1.8097x; 1.0005x over previous
#include <cuda_runtime.h>
#include <cuda_bf16.h>
#include <cstdint>

namespace {

constexpr int SQn = 2048, SKn = 2048, Dn = 128;
constexpr float SCALE = 22.62741699796952f; // 2*sqrt(128)

constexpr int STRIDE_W = 68;             // words per padded row (128 bf16 + 16B pad)
constexpr int STRIDE_B = STRIDE_W * 4;   // 272 B
constexpr int CHUNK_ROWS = 64;
constexpr int BUF_B   = CHUNK_ROWS * STRIDE_B;  // 17408 B (one of KH,KL,VH,VL)
constexpr int STAGE_B = 4 * BUF_B;              // 69632 B per stage
constexpr int NSTAGE  = 3;
constexpr int SMEM_TOTAL = NSTAGE * STAGE_B;    // 208896 B
constexpr int NCHUNK = SKn / CHUNK_ROWS;        // 32

// scratch: [bh(32)][chunk(32)][buf: KH,KL,VH,VL][row(64) * 272B]
__device__ __align__(16) char g_scratch[32ull * NCHUNK * STAGE_B];

__device__ __forceinline__ uint32_t packbf(float a, float b) {
    __nv_bfloat162 t = __floats2bfloat162_rn(a, b);
    return *reinterpret_cast<uint32_t*>(&t);
}
__device__ __forceinline__ uint32_t prmt_hi(uint32_t a, uint32_t b) {
    uint32_t d; asm("prmt.b32 %0,%1,%2,0x7632;" : "=r"(d) : "r"(a), "r"(b)); return d;
}
__device__ __forceinline__ float truncbf(float x) {
    return __uint_as_float(__float_as_uint(x) & 0xFFFF0000u);
}
__device__ __forceinline__ void mma16816(float* d, const uint32_t* a, uint32_t b0, uint32_t b1) {
    asm volatile(
        "mma.sync.aligned.m16n8k16.row.col.f32.bf16.bf16.f32 "
        "{%0,%1,%2,%3}, {%4,%5,%6,%7}, {%8,%9}, {%0,%1,%2,%3};\n"
        : "+f"(d[0]), "+f"(d[1]), "+f"(d[2]), "+f"(d[3])
        : "r"(a[0]), "r"(a[1]), "r"(a[2]), "r"(a[3]), "r"(b0), "r"(b1));
}
__device__ __forceinline__ void ldsm4(uint32_t* r, uint32_t saddr) {
    asm volatile("ldmatrix.sync.aligned.m8n8.x4.shared.b16 {%0,%1,%2,%3}, [%4];\n"
                 : "=r"(r[0]), "=r"(r[1]), "=r"(r[2]), "=r"(r[3]) : "r"(saddr));
}
__device__ __forceinline__ void ldsm4t(uint32_t* r, uint32_t saddr) {
    asm volatile("ldmatrix.sync.aligned.m8n8.x4.trans.shared.b16 {%0,%1,%2,%3}, [%4];\n"
                 : "=r"(r[0]), "=r"(r[1]), "=r"(r[2]), "=r"(r[3]) : "r"(saddr));
}
__device__ __forceinline__ void cp16(uint32_t sdst, const void* gsrc) {
    asm volatile("cp.async.cg.shared.global [%0], [%1], 16;" :: "r"(sdst), "l"(gsrc) : "memory");
}
#define CP_COMMIT() asm volatile("cp.async.commit_group;" ::: "memory")
#define CP_WAIT(n)  asm volatile("cp.async.wait_group %0;" :: "n"(n) : "memory")

__device__ __forceinline__ void bar_syncg(int id) {
    asm volatile("bar.sync %0, 256;" :: "r"(id) : "memory");
}
__device__ __forceinline__ void bar_arriveg(int id) {
    asm volatile("bar.arrive %0, 256;" :: "r"(id) : "memory");
}

// ---------------- pre-pass: K,V fp32 -> hi/lo bf16 scratch ----------------
__global__ __launch_bounds__(256) void prepass(const float* __restrict__ K,
                                               const float* __restrict__ V) {
    uint32_t g = blockIdx.x * 256u + threadIdx.x;   // 0 .. 4194303
    int c4 = g & 31;                 // float4 within row
    int r  = (g >> 5) & 2047;        // key row
    int bh = (g >> 16) & 31;
    int tv = g >> 21;                // 0 = K, 1 = V
    const float* src = (tv ? V : K) + (((size_t)bh * SKn + r) * Dn + c4 * 4);
    float4 f = *reinterpret_cast<const float4*>(src);
    uint32_t bx = __float_as_uint(f.x), by = __float_as_uint(f.y);
    uint32_t bz = __float_as_uint(f.z), bw = __float_as_uint(f.w);
    uint2 hi = make_uint2(prmt_hi(bx, by), prmt_hi(bz, bw));
    uint2 lo = make_uint2(packbf(f.x - truncbf(f.x), f.y - truncbf(f.y)),
                          packbf(f.z - truncbf(f.z), f.w - truncbf(f.w)));
    char* base = g_scratch
        + (((size_t)bh * NCHUNK + (r >> 6)) * 4 + (tv ? 2 : 0)) * (size_t)BUF_B
        + (r & 63) * STRIDE_B + c4 * 8;
    *reinterpret_cast<uint2*>(base)         = hi;
    *reinterpret_cast<uint2*>(base + BUF_B) = lo;
}

// ---------------- main kernel ----------------
__global__ __launch_bounds__(256, 1) void attn_kernel(
    const float* __restrict__ Q, const int* __restrict__ M, float* __restrict__ O)
{
    extern __shared__ char smem[];
    const uint32_t sb = (uint32_t)__cvta_generic_to_shared(smem);

    // Q overlays stage 0 (dead after fragment hoist)
    uint32_t* Qh = reinterpret_cast<uint32_t*>(smem);
    uint32_t* Ql = reinterpret_cast<uint32_t*>(smem + 2 * BUF_B);
    const uint32_t sQh = sb, sQl = sb + 2 * BUF_B;

    const int tid  = threadIdx.x;
    const int warp = tid >> 5, lane = tid & 31;
    const int gid  = lane >> 2, qid = lane & 3;
    const int qr   = warp * 16;
    const int grp  = warp >> 2;   // 0: producer+lead (rows 0-63), 1: lagging (rows 64-127)

    const int bh = blockIdx.y;
    const int qt = blockIdx.x;

    const float* Qg = Q + ((size_t)bh * SQn + (size_t)qt * 128) * Dn;
    const int*   Mg = M + ((size_t)bh * SQn + (size_t)qt * 128) * SKn;
    float*       Og = O + ((size_t)bh * SQn + (size_t)qt * 128) * Dn;
    const char*  Sg = g_scratch + (size_t)bh * NCHUNK * STAGE_B;

    // lane-derived ldmatrix offsets (bytes)
    const uint32_t bkOff = ((lane & 7) + ((lane >> 4) & 1) * 8) * STRIDE_B + ((lane >> 3) & 1) * 16;
    const uint32_t vOff  = ((lane & 7) + ((lane >> 3) & 1) * 8) * STRIDE_B + ((lane >> 4) & 1) * 16;
    const uint32_t qOff  = (qr + (lane & 15)) * STRIDE_B + ((lane >> 4) & 1) * 16;

    // ---- Q tile: global -> smem (hi/lo) ----
    {
        const float4* src = reinterpret_cast<const float4*>(Qg);
        #pragma unroll
        for (int it = 0; it < 16; ++it) {
            int idx = tid + it * 256;
            int row = idx >> 5, c4 = idx & 31;
            float4 v = src[idx];
            uint32_t bx = __float_as_uint(v.x), by = __float_as_uint(v.y);
            uint32_t bz = __float_as_uint(v.z), bw = __float_as_uint(v.w);
            int off = row * STRIDE_W + c4 * 2;
            *reinterpret_cast<uint2*>(Qh + off) = make_uint2(prmt_hi(bx, by), prmt_hi(bz, bw));
            *reinterpret_cast<uint2*>(Ql + off) =
                make_uint2(packbf(v.x - truncbf(v.x), v.y - truncbf(v.y)),
                           packbf(v.z - truncbf(v.z), v.w - truncbf(v.w)));
        }
    }
    __syncthreads();

    // ---- hoist Q fragments (invariant across chunks) ----
    uint32_t qfh[8][4], qfl[8][4];
    #pragma unroll
    for (int ds = 0; ds < 8; ++ds) {
        ldsm4(qfh[ds], sQh + qOff + ds * 32);
        ldsm4(qfl[ds], sQl + qOff + ds * 32);
    }
    __syncthreads();   // Q reads done before stage 0 is overwritten

    // ---- g0 prologue: issue chunks 0,1 into stages 0,1 ----
    if (grp == 0) {
        #pragma unroll
        for (int n = 0; n < 2; ++n) {
            const char* gb = Sg + (size_t)n * STAGE_B;
            const uint32_t sn = sb + n * STAGE_B;
            #pragma unroll 4
            for (int i = 0; i < 32; ++i) {
                int idx = i * 128 + tid;              // tid < 128 for grp 0
                int buf = idx >> 10, w = idx & 1023;
                uint32_t off = buf * BUF_B + (w >> 4) * STRIDE_B + (w & 15) * 16;
                cp16(sn + off, gb + off);
            }
            CP_COMMIT();
        }
    }

    float o[16][4];
    #pragma unroll
    for (int i = 0; i < 16; ++i)
        #pragma unroll
        for (int j = 0; j < 4; ++j) o[i][j] = 0.f;

    #pragma unroll 1
    for (int c = 0; c < NCHUNK; ++c) {
        const int st_i = c - (c / NSTAGE) * NSTAGE;     // c % 3

        // ---- acquire chunk c ----
        if (grp == 0) {
            CP_WAIT(1);          // pending <= {c+1}; chunk c complete
        } else {
            bar_syncg(1 + st_i); // g0 finished computing c
        }

        const uint32_t st = sb + st_i * STAGE_B;
        const uint32_t sKH = st, sKL = st + BUF_B, sVH = st + 2 * BUF_B, sVL = st + 3 * BUF_B;
        const int koff = c * CHUNK_ROWS;

        #pragma unroll
        for (int nc = 0; nc < 2; ++nc) {
            const int kb = nc * 32;

            // mask prefetch
            const int* m0 = Mg + (size_t)(qr + gid) * SKn + koff + kb + qid * 2;
            const int* m1 = m0 + 8 * (size_t)SKn;
            int2 ma[4], mb[4];
            #pragma unroll
            for (int j = 0; j < 4; ++j) {
                ma[j] = *reinterpret_cast<const int2*>(m0 + j * 8);
                mb[j] = *reinterpret_cast<const int2*>(m1 + j * 8);
            }

            // ---- GEMM1: S[16q x 32k] = Q·K^T (bf16x3) ----
            float s[4][4];
            #pragma unroll
            for (int j = 0; j < 4; ++j) { s[j][0]=0.f; s[j][1]=0.f; s[j][2]=0.f; s[j][3]=0.f; }

            #pragma unroll
            for (int ds = 0; ds < 8; ++ds) {
                uint32_t bh0[4], bh1[4], bl0[4], bl1[4];
                const uint32_t kcol = bkOff + ds * 32;
                ldsm4(bh0, sKH + (uint32_t)(kb     ) * STRIDE_B + kcol);
                ldsm4(bh1, sKH + (uint32_t)(kb + 16) * STRIDE_B + kcol);
                ldsm4(bl0, sKL + (uint32_t)(kb     ) * STRIDE_B + kcol);
                ldsm4(bl1, sKL + (uint32_t)(kb + 16) * STRIDE_B + kcol);
                mma16816(s[0], qfh[ds], bh0[0], bh0[1]);
                mma16816(s[1], qfh[ds], bh0[2], bh0[3]);
                mma16816(s[2], qfh[ds], bh1[0], bh1[1]);
                mma16816(s[3], qfh[ds], bh1[2], bh1[3]);
                mma16816(s[0], qfl[ds], bh0[0], bh0[1]);
                mma16816(s[1], qfl[ds], bh0[2], bh0[3]);
                mma16816(s[2], qfl[ds], bh1[0], bh1[1]);
                mma16816(s[3], qfl[ds], bh1[2], bh1[3]);
                mma16816(s[0], qfh[ds], bl0[0], bl0[1]);
                mma16816(s[1], qfh[ds], bl0[2], bl0[3]);
                mma16816(s[2], qfh[ds], bl1[0], bl1[1]);
                mma16816(s[3], qfh[ds], bl1[2], bl1[3]);
            }

            // ---- mask + scale -> P ----
            float p[4][4];
            #pragma unroll
            for (int j = 0; j < 4; ++j) {
                p[j][0] = ma[j].x ? s[j][0] * SCALE : 0.f;
                p[j][1] = ma[j].y ? s[j][1] * SCALE : 0.f;
                p[j][2] = mb[j].x ? s[j][2] * SCALE : 0.f;
                p[j][3] = mb[j].y ? s[j][3] * SCALE : 0.f;
            }

            // ---- GEMM2: O += P[16x32]·V[32x128], paired d-tiles ----
            #pragma unroll
            for (int kk = 0; kk < 2; ++kk) {
                uint32_t ahi[4], alo[4];
                {
                    const float* p0 = p[kk*2 + 0];
                    const float* p1 = p[kk*2 + 1];
                    ahi[0] = prmt_hi(__float_as_uint(p0[0]), __float_as_uint(p0[1]));
                    ahi[1] = prmt_hi(__float_as_uint(p0[2]), __float_as_uint(p0[3]));
                    ahi[2] = prmt_hi(__float_as_uint(p1[0]), __float_as_uint(p1[1]));
                    ahi[3] = prmt_hi(__float_as_uint(p1[2]), __float_as_uint(p1[3]));
                    alo[0] = packbf(p0[0] - truncbf(p0[0]), p0[1] - truncbf(p0[1]));
                    alo[1] = packbf(p0[2] - truncbf(p0[2]), p0[3] - truncbf(p0[3]));
                    alo[2] = packbf(p1[0] - truncbf(p1[0]), p1[1] - truncbf(p1[1]));
                    alo[3] = packbf(p1[2] - truncbf(p1[2]), p1[3] - truncbf(p1[3]));
                }
                const uint32_t vbase = (uint32_t)(kb + kk * 16) * STRIDE_B + vOff;

                #pragma unroll
                for (int tp = 0; tp < 4; ++tp) {
                    uint32_t vh0[4], vl0[4], vh1[4], vl1[4];
                    ldsm4t(vh0, sVH + vbase + (2*tp    ) * 32);
                    ldsm4t(vl0, sVL + vbase + (2*tp    ) * 32);
                    ldsm4t(vh1, sVH + vbase + (2*tp + 1) * 32);
                    ldsm4t(vl1, sVL + vbase + (2*tp + 1) * 32);
                    float* o0 = o[4*tp + 0];
                    float* o1 = o[4*tp + 1];
                    float* o2 = o[4*tp + 2];
                    float* o3 = o[4*tp + 3];
                    mma16816(o0, ahi, vh0[0], vh0[1]);
                    mma16816(o1, ahi, vh0[2], vh0[3]);
                    mma16816(o2, ahi, vh1[0], vh1[1]);
                    mma16816(o3, ahi, vh1[2], vh1[3]);
                    mma16816(o0, alo, vh0[0], vh0[1]);
                    mma16816(o1, alo, vh0[2], vh0[3]);
                    mma16816(o2, alo, vh1[0], vh1[1]);
                    mma16816(o3, alo, vh1[2], vh1[3]);
                    mma16816(o0, ahi, vl0[0], vl0[1]);
                    mma16816(o1, ahi, vl0[2], vl0[3]);
                    mma16816(o2, ahi, vl1[0], vl1[1]);
                    mma16816(o3, ahi, vl1[2], vl1[3]);
                }
            }
        }

        // ---- release / refill ----
        if (grp == 0) {
            bar_arriveg(1 + st_i);                     // full: g1 may start chunk c
            const int n = c + 2;
            if (n < NCHUNK) {
                const int sn_i = n - (n / NSTAGE) * NSTAGE;
                if (c >= 1) bar_syncg(4 + sn_i);       // empty: g1 finished chunk c-1
                const char* gb = Sg + (size_t)n * STAGE_B;
                const uint32_t sn = sb + sn_i * STAGE_B;
                #pragma unroll 4
                for (int i = 0; i < 32; ++i) {
                    int idx = i * 128 + tid;
                    int buf = idx >> 10, w = idx & 1023;
                    uint32_t off = buf * BUF_B + (w >> 4) * STRIDE_B + (w & 15) * 16;
                    cp16(sn + off, gb + off);
                }
            }
            CP_COMMIT();   // always commit (possibly empty group) to keep counts uniform
        } else {
            bar_arriveg(4 + st_i);                     // empty: g1 done with chunk c
        }
    }

    // ---- epilogue ----
    float* o0 = Og + (size_t)(qr + gid) * Dn + qid * 2;
    float* o1 = o0 + 8 * Dn;
    #pragma unroll
    for (int nd = 0; nd < 16; ++nd) {
        *reinterpret_cast<float2*>(o0 + nd * 8) = make_float2(o[nd][0], o[nd][1]);
        *reinterpret_cast<float2*>(o1 + nd * 8) = make_float2(o[nd][2], o[nd][3]);
    }
}

} // namespace

extern "C" void kernel_launch(void* const* d_in, const int* in_sizes, int n_in,
                              void* d_out, int out_size) {
    (void)in_sizes; (void)n_in; (void)out_size;
    const float* Q = (const float*)d_in[0];
    const float* K = (const float*)d_in[1];
    const float* V = (const float*)d_in[2];
    const int*   M = (const int*)d_in[3];
    float*       O = (float*)d_out;

    prepass<<<16384, 256>>>(K, V);

    cudaFuncSetAttribute(attn_kernel, cudaFuncAttributeMaxDynamicSharedMemorySize, SMEM_TOTAL);
    dim3 grid(SQn / 128, 32);
    attn_kernel<<<grid, 256, SMEM_TOTAL>>>(Q, M, O);
}